// round 2
// baseline (speedup 1.0000x reference)
#include <cuda_runtime.h>

#define IMG 28
#define IMG2 784              // 28*28
#define VPI 196               // float4 vectors per image
#define THREADS 256

__global__ __launch_bounds__(THREADS)
void sr_flat_kernel(const float4* __restrict__ x4,
                    const int*    __restrict__ t,
                    const float*  __restrict__ Wk,
                    const float*  __restrict__ bias,
                    float4* __restrict__ out4,
                    int total_vec)
{
    const int v = blockIdx.x * THREADS + threadIdx.x;
    if (v >= total_vec) return;

    // v -> (img, row, col0). Each float4 lies within one row (28 % 4 == 0).
    const int img  = v / VPI;
    const int rem  = v - img * VPI;
    const int row  = rem / 7;
    const int col0 = (rem - row * 7) * 4;

    const float4 val = x4[v];
    float res[4] = {val.x, val.y, val.z, val.w};

    const int tv = __ldg(&t[img]);
    const int hi = tv * tv;
    const int lo = (tv >= 1) ? (tv - 1) * (tv - 1) : -1;

    const int dr  = row - 14;
    const int dr2 = dr * dr;

    // Fast reject for the whole vector: range of dc^2 over the 4 columns.
    const int dcA = col0 - 14;
    const int dcB = col0 + 3 - 14;
    // min |dc| over [dcA, dcB]
    const int mn  = (dcA <= 0 && dcB >= 0) ? 0 : min(abs(dcA), abs(dcB));
    const int mx  = max(abs(dcA), abs(dcB));
    const int d2min = dr2 + mn * mn;
    const int d2max = dr2 + mx * mx;

    if (d2min <= hi && d2max > lo) {
        const float* base = (const float*)x4 + (size_t)img * IMG2;
        #pragma unroll
        for (int k = 0; k < 4; ++k) {
            const int col = col0 + k;
            const int dc  = col - 14;
            const int d2  = dr2 + dc * dc;
            if (d2 <= hi && d2 > lo) {
                float acc = __ldg(bias);
                #pragma unroll
                for (int ki = 0; ki < 3; ++ki) {
                    const int r = row + ki - 1;
                    if (r < 0 || r >= IMG) continue;
                    #pragma unroll
                    for (int kj = 0; kj < 3; ++kj) {
                        const int c = col + kj - 1;
                        if (c < 0 || c >= IMG) continue;
                        acc += base[r * IMG + c] * __ldg(&Wk[ki * 3 + kj]);
                    }
                }
                res[k] += acc;
            }
        }
    }

    out4[v] = make_float4(res[0], res[1], res[2], res[3]);
}

extern "C" void kernel_launch(void* const* d_in, const int* in_sizes, int n_in,
                              void* d_out, int out_size)
{
    const float4* x4   = (const float4*)d_in[0];  // [B,1,28,28] f32
    const int*    t    = (const int*)   d_in[1];  // [B] i32
    const float*  Wk   = (const float*) d_in[2];  // [1,1,3,3] f32
    const float*  bias = (const float*) d_in[3];  // [1] f32
    float4* out4 = (float4*)d_out;

    const int B = in_sizes[1];
    const int total_vec = B * VPI;
    const int blocks = (total_vec + THREADS - 1) / THREADS;
    sr_flat_kernel<<<blocks, THREADS>>>(x4, t, Wk, bias, out4, total_vec);
}